// round 6
// baseline (speedup 1.0000x reference)
#include <cuda_runtime.h>
#include <cuda_bf16.h>
#include <cstdint>

// ---------------- problem constants ----------------
#define NB      256     // bases
#define KD      768     // patch dim (3*16*16)
#define NIMG    64
#define NROW    27      // patch rows (= cols) per image
#define NPATIMG 729     // 27*27
#define NPTOT   (NIMG * NPATIMG)   // 46656
#define ITERS   50
#define NTASK   (NPTOT / 16)       // 2916 warp-tasks, exact

typedef unsigned long long u64;

// ---------------- device scratch (static: allocation-free) ----------------
__device__ float        g_gram[NB * NB];                 // D D^T - I (fp32)
__device__ float        g_b[(size_t)NPTOT * NB];         // feedforward drive (47.8 MB)
__device__ unsigned int g_maxbits[NIMG * NB];            // monotone-encoded running max
__device__ uint4        g_dfrag[48 * 32 * 32];           // D in B-frag order, hi/lo bf16
__device__ int          g_task;                          // dynamic task counter

// ---------------- generic helpers ----------------
// softshrink(-0.01*x): the code/activation given register state r = -100*u
__device__ __forceinline__ float shneg(float x) {
    float t = fmaxf(fmaf(fabsf(x), 0.01f, -0.5f), 0.0f);
    return copysignf(t, -x);
}
__device__ __forceinline__ unsigned int enc_f(float x) {
    unsigned int b = __float_as_uint(x);
    return (b & 0x80000000u) ? ~b : (b | 0x80000000u);
}
__device__ __forceinline__ uint32_t bf2u(float a, float b) {
    __nv_bfloat162 h = __float22bfloat162_rn(make_float2(a, b));
    return *reinterpret_cast<uint32_t*>(&h);
}
__device__ __forceinline__ float bfh(float v) {
    return __bfloat162float(__float2bfloat16_rn(v));
}
// m16n8k16 row.col bf16 -> f32, D accumulated in place
__device__ __forceinline__ void mma16816(float d[4], uint32_t a0, uint32_t a1,
                                         uint32_t a2, uint32_t a3,
                                         uint32_t b0, uint32_t b1) {
    asm volatile(
        "mma.sync.aligned.m16n8k16.row.col.f32.bf16.bf16.f32 "
        "{%0,%1,%2,%3}, {%4,%5,%6,%7}, {%8,%9}, {%0,%1,%2,%3};"
        : "+f"(d[0]), "+f"(d[1]), "+f"(d[2]), "+f"(d[3])
        : "r"(a0), "r"(a1), "r"(a2), "r"(a3), "r"(b0), "r"(b1));
}

// ---------------- K0: init running max + task counter ----------------
__global__ void init_kernel() {
    g_maxbits[blockIdx.x * NB + threadIdx.x] = 0u;
    if (blockIdx.x == 0 && threadIdx.x == 0) g_task = 0;
}

// ---------------- K1: gram = D D^T - I ----------------
__global__ void __launch_bounds__(256) gram_kernel(const float* __restrict__ D) {
    __shared__ float di[KD];
    const int i = blockIdx.x;
    const int t = threadIdx.x;

    const float4* Di4 = (const float4*)(D + (size_t)i * KD);
    for (int q = t; q < KD / 4; q += 256) ((float4*)di)[q] = Di4[q];
    __syncthreads();

    const float4* Dj4 = (const float4*)(D + (size_t)t * KD);
    float acc = 0.f;
    #pragma unroll 4
    for (int q = 0; q < KD / 4; q++) {
        float4 v = __ldg(&Dj4[q]);
        acc += v.x * di[4*q] + v.y * di[4*q+1] + v.z * di[4*q+2] + v.w * di[4*q+3];
    }
    g_gram[i * NB + t] = acc - ((i == t) ? 1.0f : 0.0f);
}

// ---------------- K1b: pre-fragment D (hi/lo bf16) into B-frag order ----------------
__global__ void __launch_bounds__(256) dfrag_kernel(const float* __restrict__ D) {
    int e = blockIdx.x * 256 + threadIdx.x;       // grid 192 -> 49152
    int kk = e >> 10;
    int j  = (e >> 5) & 31;
    int ln = e & 31;
    int k0 = kk * 16 + 2 * (ln & 3);
    int n  = j * 8 + (ln >> 2);
    const float* Dr = D + (size_t)n * KD;
    float v00 = __ldg(Dr + k0),     v01 = __ldg(Dr + k0 + 1);
    float v08 = __ldg(Dr + k0 + 8), v09 = __ldg(Dr + k0 + 9);
    uint4 q;
    q.x = bf2u(v00, v01);
    q.y = bf2u(v08, v09);
    q.z = bf2u(v00 - bfh(v00), v01 - bfh(v01));
    q.w = bf2u(v08 - bfh(v08), v09 - bfh(v09));
    g_dfrag[e] = q;
}

// ---------------- K2: b = standardized_patches @ D^T via mma (hi/lo split) ----------------
// One CTA = one image x 4 patch rows (108 patches, M=128 padded). 512 threads,
// warp grid 4M x 4N. A staged pre-converted as packed {hi,lo} bf16 pairs.
#define BSM_STAT  107520                     // strip = 3*40*224 floats before this
#define BSM_A     108544                     // A chunk: [128][36] uint2 = 36864 B
#define BSM_B     145408                     // B chunk: [4][32][32] uint4 = 65536 B
#define B2_SMEM   (BSM_B + 65536)            // 210944 B

__global__ void __launch_bounds__(512, 1) b_mma_kernel(const float* __restrict__ img) {
    extern __shared__ char sm[];
    float* strip  = (float*)sm;                    // [3][40][224]
    float* mean_s = (float*)(sm + BSM_STAT);       // [128]
    float* inv_s  = mean_s + 128;
    uint2* Apk    = (uint2*)(sm + BSM_A);          // [128][36] {hi,lo} k-pairs
    uint4* Bsm    = (uint4*)(sm + BSM_B);          // [4*32*32]

    const int blk  = blockIdx.x;
    const int im   = blk / 7;
    const int band = blk - im * 7;
    const int py0  = band * 4;
    const int nr   = (band == 6) ? 3 : 4;
    const int npat = 27 * nr;
    const int srows = 8 * nr + 8;
    const int t = threadIdx.x;

    // ---- load strip ----
    const float* ib = img + (size_t)im * 3 * 224 * 224 + (size_t)(py0 * 8) * 224;
    const int tot = 3 * srows * 224;
    for (int e = t; e < tot; e += 512) {
        int c   = e / (srows * 224);
        int rem = e - c * (srows * 224);
        strip[(c * 40) * 224 + rem] = ib[(size_t)c * 224 * 224 + rem];
    }
    __syncthreads();

    // ---- per-patch stats: 4 lanes per patch ----
    {
        int p0 = t >> 2;
        int p  = (p0 < npat) ? p0 : (npat - 1);
        int l4 = t & 3;
        int pr = p / 27, pc = p - pr * 27;
        int y0 = pr * 8, x0 = pc * 8;
        float sm_ = 0.f, sq = 0.f;
        for (int d = l4; d < KD; d += 4) {
            int c   = d >> 8;
            int r16 = (d >> 4) & 15;
            int pw  = d & 15;
            float v = strip[(c * 40 + y0 + r16) * 224 + x0 + pw];
            sm_ += v; sq += v * v;
        }
        sm_ += __shfl_down_sync(0xffffffffu, sm_, 2);
        sq  += __shfl_down_sync(0xffffffffu, sq,  2);
        sm_ += __shfl_down_sync(0xffffffffu, sm_, 1);
        sq  += __shfl_down_sync(0xffffffffu, sq,  1);
        if (l4 == 0 && p0 < npat) {
            float m   = sm_ * (1.0f / 768.0f);
            float var = fmaxf(sq - sm_ * sm_ * (1.0f / 768.0f), 0.0f) * (1.0f / 767.0f);
            mean_s[p0] = m;
            inv_s[p0]  = 1.0f / (sqrtf(var) + 1e-8f);
        }
    }

    const int w    = t >> 5;
    const int lane = t & 31;
    const int wm   = w & 3;
    const int wn   = w >> 2;
    const int row  = lane >> 2;
    const int l4   = lane & 3;

    float acc[2][8][4];
    #pragma unroll
    for (int mt = 0; mt < 2; mt++)
        #pragma unroll
        for (int j = 0; j < 8; j++)
            #pragma unroll
            for (int c = 0; c < 4; c++) acc[mt][j][c] = 0.f;

    // thread's A-staging identity
    const int  am  = t >> 2;
    const bool amv = am < npat;
    const int  apr = amv ? am / 27 : 0;
    const int  apc = amv ? (am - apr * 27) : 0;

    __syncthreads();   // stats visible

    const float amm = amv ? mean_s[am] : 0.f;
    const float aiv = amv ? inv_s[am]  : 0.f;

    // ---- main k loop: 12 chunks of 64 ----
    #pragma unroll 1
    for (int ch = 0; ch < 12; ch++) {
        const int kc0 = ch * 64;
        // stage A chunk: standardized values as packed {hi, lo} bf16 k-pairs
        #pragma unroll
        for (int i = 0; i < 8; i++) {
            int p2 = (t & 3) * 8 + i;          // pair index 0..31
            int d  = kc0 + 2 * p2;
            int c   = d >> 8;
            int r16 = (d >> 4) & 15;
            int pw  = d & 15;
            float v0 = 0.f, v1 = 0.f;
            if (amv) {
                const float* sp = &strip[(c * 40 + apr * 8 + r16) * 224 + apc * 8 + pw];
                v0 = (sp[0] - amm) * aiv;
                v1 = (sp[1] - amm) * aiv;
            }
            uint2 pk;
            pk.x = bf2u(v0, v1);
            pk.y = bf2u(v0 - bfh(v0), v1 - bfh(v1));
            Apk[am * 36 + p2] = pk;
        }
        // stage B chunk (64KB contiguous)
        const uint4* gsrc = g_dfrag + (size_t)ch * 4096;
        #pragma unroll
        for (int e = t; e < 4096; e += 512) Bsm[e] = __ldg(&gsrc[e]);
        __syncthreads();

        #pragma unroll
        for (int kkl = 0; kkl < 4; kkl++) {
            uint2 aa[2][4];
            #pragma unroll
            for (int mt = 0; mt < 2; mt++) {
                int mrow = wm * 32 + mt * 16 + row;
                aa[mt][0] = Apk[mrow * 36 + kkl * 8 + l4];
                aa[mt][1] = Apk[(mrow + 8) * 36 + kkl * 8 + l4];
                aa[mt][2] = Apk[mrow * 36 + kkl * 8 + 4 + l4];
                aa[mt][3] = Apk[(mrow + 8) * 36 + kkl * 8 + 4 + l4];
            }
            #pragma unroll
            for (int j = 0; j < 8; j++) {
                uint4 q = Bsm[(kkl * 32 + wn * 8 + j) * 32 + lane];
                #pragma unroll
                for (int mt = 0; mt < 2; mt++) {
                    mma16816(acc[mt][j], aa[mt][0].x, aa[mt][1].x, aa[mt][2].x, aa[mt][3].x, q.x, q.y);
                    mma16816(acc[mt][j], aa[mt][0].x, aa[mt][1].x, aa[mt][2].x, aa[mt][3].x, q.z, q.w);
                    mma16816(acc[mt][j], aa[mt][0].y, aa[mt][1].y, aa[mt][2].y, aa[mt][3].y, q.x, q.y);
                }
            }
        }
        __syncthreads();   // before restaging
    }

    // ---- epilogue: write b ----
    const int pbase = (im * NROW + py0) * NROW;
    const int kp = 2 * l4;
    #pragma unroll
    for (int mt = 0; mt < 2; mt++) {
        int m0 = wm * 32 + mt * 16 + row;
        int m1 = m0 + 8;
        #pragma unroll
        for (int j = 0; j < 8; j++) {
            int n0 = wn * 64 + j * 8 + kp;
            if (m0 < npat) {
                int gp = pbase + (m0 / 27) * NROW + (m0 % 27);
                *(float2*)(g_b + (size_t)gp * NB + n0) = make_float2(acc[mt][j][0], acc[mt][j][1]);
            }
            if (m1 < npat) {
                int gp = pbase + (m1 / 27) * NROW + (m1 % 27);
                *(float2*)(g_b + (size_t)gp * NB + n0) = make_float2(acc[mt][j][2], acc[mt][j][3]);
            }
        }
    }
}

// ---------------- K3: persistent LCA via mma.sync, dynamic warp-tasks ----------------
// 148 CTAs x 384 threads. gram staged once per CTA (128 KB). Each warp fetches
// 16-patch tasks from a global counter; 2916 tasks total (exact, no masks).
#define LCA_SMEM 131072

__global__ void __launch_bounds__(384, 1) lca_persist_kernel() {
    extern __shared__ uint4 bsm4[];            // [8192] paired gram frags
    const int tid  = threadIdx.x;
    const int lane = tid & 31;

    // stage gram (bf16) paired: entry (kk*16 + j)*32 + ln holds frags for
    // n-tiles j and j+16:  k0 = kk*16 + 2(ln&3), n1 = j*8 + (ln>>2), n2 = n1 + 128
    for (int e = tid; e < 8192; e += 384) {
        int kk = e >> 9;
        int j  = (e >> 5) & 15;
        int ln = e & 31;
        int k0 = kk * 16 + 2 * (ln & 3);
        int n1 = j * 8 + (ln >> 2);
        int n2 = n1 + 128;
        uint4 q;
        q.x = bf2u(g_gram[k0 * NB + n1],       g_gram[(k0 + 1) * NB + n1]);
        q.y = bf2u(g_gram[(k0 + 8) * NB + n1], g_gram[(k0 + 9) * NB + n1]);
        q.z = bf2u(g_gram[k0 * NB + n2],       g_gram[(k0 + 1) * NB + n2]);
        q.w = bf2u(g_gram[(k0 + 8) * NB + n2], g_gram[(k0 + 9) * NB + n2]);
        bsm4[e] = q;
    }
    __syncthreads();

    const uint4* bwl = bsm4 + lane;

    while (true) {
        int task;
        if (lane == 0) task = atomicAdd(&g_task, 1);
        task = __shfl_sync(0xffffffffu, task, 0);
        if (task >= NTASK) break;

        const int base = task * 16;
        const int gpl  = base + (lane >> 2);
        const float2* blf = (const float2*)(g_b + (size_t)gpl * NB + 2 * (lane & 3));
        const float2* bhf = (const float2*)(g_b + (size_t)(gpl + 8) * NB + 2 * (lane & 3));

        // ---- warm start: max |b| over the warp's 16x256 block ----
        float mx = 0.f;
        #pragma unroll
        for (int j = 0; j < 32; j++) {
            float2 x = __ldg(blf + 4 * j);
            float2 y = __ldg(bhf + 4 * j);
            mx = fmaxf(mx, fmaxf(fmaxf(fabsf(x.x), fabsf(x.y)),
                                 fmaxf(fabsf(y.x), fabsf(y.y))));
        }
        float m1 = __uint_as_float(__reduce_max_sync(0xffffffffu, __float_as_uint(mx)));

        int S = 0; float gg = 1.0f;
        while (S < ITERS - 1 && (1.0f - gg) * m1 < 0.4999f) { S++; gg *= 0.99f; }
        const int   R = ITERS - S;
        const float f = -(1.0f - gg) * 100.0f;   // r = -100 * u

        float r[32][4];
        #pragma unroll
        for (int j = 0; j < 32; j++) {
            float2 x = __ldg(blf + 4 * j);
            float2 y = __ldg(bhf + 4 * j);
            r[j][0] = f * x.x;
            r[j][1] = f * x.y;
            r[j][2] = f * y.x;
            r[j][3] = f * y.y;
        }

        #pragma unroll 1
        for (int it = 0; it < R; it++) {
            uint32_t a[16][4];
            #pragma unroll
            for (int kk = 0; kk < 16; kk++) {
                a[kk][0] = bf2u(shneg(r[2*kk][0]),   shneg(r[2*kk][1]));
                a[kk][1] = bf2u(shneg(r[2*kk][2]),   shneg(r[2*kk][3]));
                a[kk][2] = bf2u(shneg(r[2*kk+1][0]), shneg(r[2*kk+1][1]));
                a[kk][3] = bf2u(shneg(r[2*kk+1][2]), shneg(r[2*kk+1][3]));
            }
            #pragma unroll
            for (int j = 0; j < 32; j++) {
                float2 x = __ldg(blf + 4 * j);
                float2 y = __ldg(bhf + 4 * j);
                r[j][0] = fmaf(r[j][0], 0.99f, -x.x);
                r[j][1] = fmaf(r[j][1], 0.99f, -x.y);
                r[j][2] = fmaf(r[j][2], 0.99f, -y.x);
                r[j][3] = fmaf(r[j][3], 0.99f, -y.y);
            }
            #pragma unroll
            for (int kk = 0; kk < 16; kk++) {
                #pragma unroll
                for (int j = 0; j < 16; j++) {
                    uint4 q = bwl[(kk * 16 + j) * 32];
                    mma16816(r[j],      a[kk][0], a[kk][1], a[kk][2], a[kk][3], q.x, q.y);
                    mma16816(r[j + 16], a[kk][0], a[kk][1], a[kk][2], a[kk][3], q.z, q.w);
                }
            }
        }

        // ---- epilogue: codes = shneg(r); warp-reduced max, direct global atomics ----
        const int im0 = base / NPATIMG;
        const int im1 = (base + 15) / NPATIMG;
        if (im0 == im1) {
            // all 16 rows in one image: butterfly over the 8 lanes sharing (lane&3)
            #pragma unroll
            for (int j = 0; j < 32; j++) {
                unsigned e0 = max(enc_f(shneg(r[j][0])), enc_f(shneg(r[j][2])));
                unsigned e1 = max(enc_f(shneg(r[j][1])), enc_f(shneg(r[j][3])));
                #pragma unroll
                for (int o = 4; o < 32; o <<= 1) {
                    e0 = max(e0, __shfl_xor_sync(0xffffffffu, e0, o));
                    e1 = max(e1, __shfl_xor_sync(0xffffffffu, e1, o));
                }
                if (lane < 4) {
                    int n0 = 8 * j + 2 * lane;
                    atomicMax(&g_maxbits[im0 * NB + n0],     e0);
                    atomicMax(&g_maxbits[im0 * NB + n0 + 1], e1);
                }
            }
        } else {
            // straddles an image boundary (rare): per-element atomics
            const int iml = gpl / NPATIMG;
            const int imh = (gpl + 8) / NPATIMG;
            #pragma unroll
            for (int j = 0; j < 32; j++) {
                int n0 = 8 * j + 2 * (lane & 3);
                atomicMax(&g_maxbits[iml * NB + n0],     enc_f(shneg(r[j][0])));
                atomicMax(&g_maxbits[iml * NB + n0 + 1], enc_f(shneg(r[j][1])));
                atomicMax(&g_maxbits[imh * NB + n0],     enc_f(shneg(r[j][2])));
                atomicMax(&g_maxbits[imh * NB + n0 + 1], enc_f(shneg(r[j][3])));
            }
        }
    }
}

// ---------------- K4: decode running max to output ----------------
__global__ void finalize_kernel(float* __restrict__ out) {
    int idx = blockIdx.x * NB + threadIdx.x;
    unsigned int k = g_maxbits[idx];
    out[idx] = (k & 0x80000000u) ? __uint_as_float(k & 0x7fffffffu)
                                 : __uint_as_float(~k);
}

// ---------------- launch ----------------
extern "C" void kernel_launch(void* const* d_in, const int* in_sizes, int n_in,
                              void* d_out, int out_size) {
    const float* image = (const float*)d_in[0];
    const float* dict  = (const float*)d_in[1];
    float* out = (float*)d_out;

    cudaFuncSetAttribute(b_mma_kernel,       cudaFuncAttributeMaxDynamicSharedMemorySize, B2_SMEM);
    cudaFuncSetAttribute(lca_persist_kernel, cudaFuncAttributeMaxDynamicSharedMemorySize, LCA_SMEM);

    init_kernel<<<NIMG, NB>>>();
    gram_kernel<<<NB, 256>>>(dict);
    dfrag_kernel<<<192, 256>>>(dict);
    b_mma_kernel<<<NIMG * 7, 512, B2_SMEM>>>(image);
    lca_persist_kernel<<<148, 384, LCA_SMEM>>>();
    finalize_kernel<<<NIMG, NB>>>(out);
}

// round 7
// speedup vs baseline: 1.2392x; 1.2392x over previous
#include <cuda_runtime.h>
#include <cuda_bf16.h>
#include <cstdint>

// ---------------- problem constants ----------------
#define NB      256     // bases
#define KD      768     // patch dim (3*16*16)
#define NIMG    64
#define NROW    27      // patch rows (= cols) per image
#define NPATIMG 729     // 27*27
#define NPTOT   (NIMG * NPATIMG)   // 46656
#define ITERS   50
#define NTASK   (NPTOT / 16)       // 2916 warp-tasks, exact

typedef unsigned long long u64;

// ---------------- device scratch (static: allocation-free) ----------------
__device__ float        g_gram[NB * NB];                 // D D^T - I (fp32)
__device__ float        g_b[(size_t)NPTOT * NB];         // feedforward drive (47.8 MB)
__device__ unsigned int g_maxbits[NIMG * NB];            // monotone-encoded running max
__device__ uint4        g_dfrag[48 * 32 * 32];           // D in B-frag order, hi/lo bf16
__device__ int          g_task;                          // dynamic task counter

// ---------------- generic helpers ----------------
// softshrink(-0.01*x): the code/activation given register state r = -100*u
__device__ __forceinline__ float shneg(float x) {
    float t = fmaxf(fmaf(fabsf(x), 0.01f, -0.5f), 0.0f);
    return copysignf(t, -x);
}
__device__ __forceinline__ unsigned int enc_f(float x) {
    unsigned int b = __float_as_uint(x);
    return (b & 0x80000000u) ? ~b : (b | 0x80000000u);
}
__device__ __forceinline__ uint32_t bf2u(float a, float b) {
    __nv_bfloat162 h = __float22bfloat162_rn(make_float2(a, b));
    return *reinterpret_cast<uint32_t*>(&h);
}
__device__ __forceinline__ float bfh(float v) {
    return __bfloat162float(__float2bfloat16_rn(v));
}
// m16n8k16 row.col bf16 -> f32, D accumulated in place
__device__ __forceinline__ void mma16816(float d[4], uint32_t a0, uint32_t a1,
                                         uint32_t a2, uint32_t a3,
                                         uint32_t b0, uint32_t b1) {
    asm volatile(
        "mma.sync.aligned.m16n8k16.row.col.f32.bf16.bf16.f32 "
        "{%0,%1,%2,%3}, {%4,%5,%6,%7}, {%8,%9}, {%0,%1,%2,%3};"
        : "+f"(d[0]), "+f"(d[1]), "+f"(d[2]), "+f"(d[3])
        : "r"(a0), "r"(a1), "r"(a2), "r"(a3), "r"(b0), "r"(b1));
}

// ---------------- K0: init running max + task counter ----------------
__global__ void init_kernel() {
    g_maxbits[blockIdx.x * NB + threadIdx.x] = 0u;
    if (blockIdx.x == 0 && threadIdx.x == 0) g_task = 0;
}

// ---------------- K1: gram = D D^T - I ----------------
__global__ void __launch_bounds__(256) gram_kernel(const float* __restrict__ D) {
    __shared__ float di[KD];
    const int i = blockIdx.x;
    const int t = threadIdx.x;

    const float4* Di4 = (const float4*)(D + (size_t)i * KD);
    for (int q = t; q < KD / 4; q += 256) ((float4*)di)[q] = Di4[q];
    __syncthreads();

    const float4* Dj4 = (const float4*)(D + (size_t)t * KD);
    float acc = 0.f;
    #pragma unroll 4
    for (int q = 0; q < KD / 4; q++) {
        float4 v = __ldg(&Dj4[q]);
        acc += v.x * di[4*q] + v.y * di[4*q+1] + v.z * di[4*q+2] + v.w * di[4*q+3];
    }
    g_gram[i * NB + t] = acc - ((i == t) ? 1.0f : 0.0f);
}

// ---------------- K1b: pre-fragment D (hi/lo bf16) into B-frag order ----------------
__global__ void __launch_bounds__(256) dfrag_kernel(const float* __restrict__ D) {
    int e = blockIdx.x * 256 + threadIdx.x;       // grid 192 -> 49152
    int kk = e >> 10;
    int j  = (e >> 5) & 31;
    int ln = e & 31;
    int k0 = kk * 16 + 2 * (ln & 3);
    int n  = j * 8 + (ln >> 2);
    const float* Dr = D + (size_t)n * KD;
    float v00 = __ldg(Dr + k0),     v01 = __ldg(Dr + k0 + 1);
    float v08 = __ldg(Dr + k0 + 8), v09 = __ldg(Dr + k0 + 9);
    uint4 q;
    q.x = bf2u(v00, v01);
    q.y = bf2u(v08, v09);
    q.z = bf2u(v00 - bfh(v00), v01 - bfh(v01));
    q.w = bf2u(v08 - bfh(v08), v09 - bfh(v09));
    g_dfrag[e] = q;
}

// ---------------- K2: b = standardized_patches @ D^T via mma (hi/lo split) ----------------
// One CTA = one image x 4 patch rows (108 patches, M=128 padded). 512 threads,
// warp grid 4M x 4N. A staged pre-converted as packed {hi,lo} bf16 pairs.
#define BSM_STAT  107520                     // strip = 3*40*224 floats before this
#define BSM_A     108544                     // A chunk: [128][36] uint2 = 36864 B
#define BSM_B     145408                     // B chunk: [4][32][32] uint4 = 65536 B
#define B2_SMEM   (BSM_B + 65536)            // 210944 B

__global__ void __launch_bounds__(512, 1) b_mma_kernel(const float* __restrict__ img) {
    extern __shared__ char sm[];
    float* strip  = (float*)sm;                    // [3][40][224]
    float* mean_s = (float*)(sm + BSM_STAT);       // [128]
    float* inv_s  = mean_s + 128;
    uint2* Apk    = (uint2*)(sm + BSM_A);          // [128][36] {hi,lo} k-pairs
    uint4* Bsm    = (uint4*)(sm + BSM_B);          // [4*32*32]

    const int blk  = blockIdx.x;
    const int im   = blk / 7;
    const int band = blk - im * 7;
    const int py0  = band * 4;
    const int nr   = (band == 6) ? 3 : 4;
    const int npat = 27 * nr;
    const int srows = 8 * nr + 8;
    const int t = threadIdx.x;

    // ---- load strip ----
    const float* ib = img + (size_t)im * 3 * 224 * 224 + (size_t)(py0 * 8) * 224;
    const int tot = 3 * srows * 224;
    for (int e = t; e < tot; e += 512) {
        int c   = e / (srows * 224);
        int rem = e - c * (srows * 224);
        strip[(c * 40) * 224 + rem] = ib[(size_t)c * 224 * 224 + rem];
    }
    __syncthreads();

    // ---- per-patch stats: 4 lanes per patch ----
    {
        int p0 = t >> 2;
        int p  = (p0 < npat) ? p0 : (npat - 1);
        int l4 = t & 3;
        int pr = p / 27, pc = p - pr * 27;
        int y0 = pr * 8, x0 = pc * 8;
        float sm_ = 0.f, sq = 0.f;
        for (int d = l4; d < KD; d += 4) {
            int c   = d >> 8;
            int r16 = (d >> 4) & 15;
            int pw  = d & 15;
            float v = strip[(c * 40 + y0 + r16) * 224 + x0 + pw];
            sm_ += v; sq += v * v;
        }
        sm_ += __shfl_down_sync(0xffffffffu, sm_, 2);
        sq  += __shfl_down_sync(0xffffffffu, sq,  2);
        sm_ += __shfl_down_sync(0xffffffffu, sm_, 1);
        sq  += __shfl_down_sync(0xffffffffu, sq,  1);
        if (l4 == 0 && p0 < npat) {
            float m   = sm_ * (1.0f / 768.0f);
            float var = fmaxf(sq - sm_ * sm_ * (1.0f / 768.0f), 0.0f) * (1.0f / 767.0f);
            mean_s[p0] = m;
            inv_s[p0]  = 1.0f / (sqrtf(var) + 1e-8f);
        }
    }

    const int w    = t >> 5;
    const int lane = t & 31;
    const int wm   = w & 3;
    const int wn   = w >> 2;
    const int row  = lane >> 2;
    const int l4   = lane & 3;

    float acc[2][8][4];
    #pragma unroll
    for (int mt = 0; mt < 2; mt++)
        #pragma unroll
        for (int j = 0; j < 8; j++)
            #pragma unroll
            for (int c = 0; c < 4; c++) acc[mt][j][c] = 0.f;

    // thread's A-staging identity
    const int  am  = t >> 2;
    const bool amv = am < npat;
    const int  apr = amv ? am / 27 : 0;
    const int  apc = amv ? (am - apr * 27) : 0;

    __syncthreads();   // stats visible

    const float amm = amv ? mean_s[am] : 0.f;
    const float aiv = amv ? inv_s[am]  : 0.f;

    // ---- main k loop: 12 chunks of 64 ----
    #pragma unroll 1
    for (int ch = 0; ch < 12; ch++) {
        const int kc0 = ch * 64;
        // stage A chunk: standardized values as packed {hi, lo} bf16 k-pairs
        #pragma unroll
        for (int i = 0; i < 8; i++) {
            int p2 = (t & 3) * 8 + i;          // pair index 0..31
            int d  = kc0 + 2 * p2;
            int c   = d >> 8;
            int r16 = (d >> 4) & 15;
            int pw  = d & 15;
            float v0 = 0.f, v1 = 0.f;
            if (amv) {
                const float* sp = &strip[(c * 40 + apr * 8 + r16) * 224 + apc * 8 + pw];
                v0 = (sp[0] - amm) * aiv;
                v1 = (sp[1] - amm) * aiv;
            }
            uint2 pk;
            pk.x = bf2u(v0, v1);
            pk.y = bf2u(v0 - bfh(v0), v1 - bfh(v1));
            Apk[am * 36 + p2] = pk;
        }
        // stage B chunk (64KB contiguous)
        const uint4* gsrc = g_dfrag + (size_t)ch * 4096;
        #pragma unroll
        for (int e = t; e < 4096; e += 512) Bsm[e] = __ldg(&gsrc[e]);
        __syncthreads();

        #pragma unroll
        for (int kkl = 0; kkl < 4; kkl++) {
            uint2 aa[2][4];
            #pragma unroll
            for (int mt = 0; mt < 2; mt++) {
                int mrow = wm * 32 + mt * 16 + row;
                aa[mt][0] = Apk[mrow * 36 + kkl * 8 + l4];
                aa[mt][1] = Apk[(mrow + 8) * 36 + kkl * 8 + l4];
                aa[mt][2] = Apk[mrow * 36 + kkl * 8 + 4 + l4];
                aa[mt][3] = Apk[(mrow + 8) * 36 + kkl * 8 + 4 + l4];
            }
            #pragma unroll
            for (int j = 0; j < 8; j++) {
                uint4 q = Bsm[(kkl * 32 + wn * 8 + j) * 32 + lane];
                #pragma unroll
                for (int mt = 0; mt < 2; mt++) {
                    mma16816(acc[mt][j], aa[mt][0].x, aa[mt][1].x, aa[mt][2].x, aa[mt][3].x, q.x, q.y);
                    mma16816(acc[mt][j], aa[mt][0].x, aa[mt][1].x, aa[mt][2].x, aa[mt][3].x, q.z, q.w);
                    mma16816(acc[mt][j], aa[mt][0].y, aa[mt][1].y, aa[mt][2].y, aa[mt][3].y, q.x, q.y);
                }
            }
        }
        __syncthreads();   // before restaging
    }

    // ---- epilogue: write b ----
    const int pbase = (im * NROW + py0) * NROW;
    const int kp = 2 * l4;
    #pragma unroll
    for (int mt = 0; mt < 2; mt++) {
        int m0 = wm * 32 + mt * 16 + row;
        int m1 = m0 + 8;
        #pragma unroll
        for (int j = 0; j < 8; j++) {
            int n0 = wn * 64 + j * 8 + kp;
            if (m0 < npat) {
                int gp = pbase + (m0 / 27) * NROW + (m0 % 27);
                *(float2*)(g_b + (size_t)gp * NB + n0) = make_float2(acc[mt][j][0], acc[mt][j][1]);
            }
            if (m1 < npat) {
                int gp = pbase + (m1 / 27) * NROW + (m1 % 27);
                *(float2*)(g_b + (size_t)gp * NB + n0) = make_float2(acc[mt][j][2], acc[mt][j][3]);
            }
        }
    }
}

// ---------------- K3: persistent LCA via mma.sync, dynamic warp-tasks ----------------
// 148 CTAs x 256 threads (8 warps -> 255-reg budget, NO spills). gram staged once
// per CTA. Warps fetch 16-patch tasks from a global counter; 2916 tasks exact.
#define LCA_SMEM 131072

__global__ void __launch_bounds__(256, 1) lca_persist_kernel() {
    extern __shared__ uint4 bsm4[];            // [8192] paired gram frags
    const int tid  = threadIdx.x;
    const int lane = tid & 31;

    // stage gram (bf16) paired: entry (kk*16 + j)*32 + ln holds frags for
    // n-tiles j and j+16:  k0 = kk*16 + 2(ln&3), n1 = j*8 + (ln>>2), n2 = n1 + 128
    for (int e = tid; e < 8192; e += 256) {
        int kk = e >> 9;
        int j  = (e >> 5) & 15;
        int ln = e & 31;
        int k0 = kk * 16 + 2 * (ln & 3);
        int n1 = j * 8 + (ln >> 2);
        int n2 = n1 + 128;
        uint4 q;
        q.x = bf2u(g_gram[k0 * NB + n1],       g_gram[(k0 + 1) * NB + n1]);
        q.y = bf2u(g_gram[(k0 + 8) * NB + n1], g_gram[(k0 + 9) * NB + n1]);
        q.z = bf2u(g_gram[k0 * NB + n2],       g_gram[(k0 + 1) * NB + n2]);
        q.w = bf2u(g_gram[(k0 + 8) * NB + n2], g_gram[(k0 + 9) * NB + n2]);
        bsm4[e] = q;
    }
    __syncthreads();

    const uint4* bwl = bsm4 + lane;

    while (true) {
        int task;
        if (lane == 0) task = atomicAdd(&g_task, 1);
        task = __shfl_sync(0xffffffffu, task, 0);
        if (task >= NTASK) break;

        const int base = task * 16;
        const int gpl  = base + (lane >> 2);
        const float2* blf = (const float2*)(g_b + (size_t)gpl * NB + 2 * (lane & 3));
        const float2* bhf = (const float2*)(g_b + (size_t)(gpl + 8) * NB + 2 * (lane & 3));

        // ---- warm start: max |b| over the warp's 16x256 block ----
        float mx = 0.f;
        #pragma unroll
        for (int j = 0; j < 32; j++) {
            float2 x = __ldg(blf + 4 * j);
            float2 y = __ldg(bhf + 4 * j);
            mx = fmaxf(mx, fmaxf(fmaxf(fabsf(x.x), fabsf(x.y)),
                                 fmaxf(fabsf(y.x), fabsf(y.y))));
        }
        float m1 = __uint_as_float(__reduce_max_sync(0xffffffffu, __float_as_uint(mx)));

        int S = 0; float gg = 1.0f;
        while (S < ITERS - 1 && (1.0f - gg) * m1 < 0.4999f) { S++; gg *= 0.99f; }
        const int   R = ITERS - S;
        const float f = -(1.0f - gg) * 100.0f;   // r = -100 * u

        float r[32][4];
        #pragma unroll
        for (int j = 0; j < 32; j++) {
            float2 x = __ldg(blf + 4 * j);
            float2 y = __ldg(bhf + 4 * j);
            r[j][0] = f * x.x;
            r[j][1] = f * x.y;
            r[j][2] = f * y.x;
            r[j][3] = f * y.y;
        }

        #pragma unroll 1
        for (int it = 0; it < R; it++) {
            uint32_t a[16][4];
            #pragma unroll
            for (int kk = 0; kk < 16; kk++) {
                a[kk][0] = bf2u(shneg(r[2*kk][0]),   shneg(r[2*kk][1]));
                a[kk][1] = bf2u(shneg(r[2*kk][2]),   shneg(r[2*kk][3]));
                a[kk][2] = bf2u(shneg(r[2*kk+1][0]), shneg(r[2*kk+1][1]));
                a[kk][3] = bf2u(shneg(r[2*kk+1][2]), shneg(r[2*kk+1][3]));
            }
            #pragma unroll
            for (int j = 0; j < 32; j++) {
                float2 x = __ldg(blf + 4 * j);
                float2 y = __ldg(bhf + 4 * j);
                r[j][0] = fmaf(r[j][0], 0.99f, -x.x);
                r[j][1] = fmaf(r[j][1], 0.99f, -x.y);
                r[j][2] = fmaf(r[j][2], 0.99f, -y.x);
                r[j][3] = fmaf(r[j][3], 0.99f, -y.y);
            }
            #pragma unroll
            for (int kk = 0; kk < 16; kk++) {
                #pragma unroll
                for (int j = 0; j < 16; j++) {
                    uint4 q = bwl[(kk * 16 + j) * 32];
                    mma16816(r[j],      a[kk][0], a[kk][1], a[kk][2], a[kk][3], q.x, q.y);
                    mma16816(r[j + 16], a[kk][0], a[kk][1], a[kk][2], a[kk][3], q.z, q.w);
                }
            }
        }

        // ---- epilogue: codes = shneg(r); warp-reduced max, direct global atomics ----
        const int im0 = base / NPATIMG;
        const int im1 = (base + 15) / NPATIMG;
        if (im0 == im1) {
            // all 16 rows in one image: butterfly over the 8 lanes sharing (lane&3)
            #pragma unroll
            for (int j = 0; j < 32; j++) {
                unsigned e0 = max(enc_f(shneg(r[j][0])), enc_f(shneg(r[j][2])));
                unsigned e1 = max(enc_f(shneg(r[j][1])), enc_f(shneg(r[j][3])));
                #pragma unroll
                for (int o = 4; o < 32; o <<= 1) {
                    e0 = max(e0, __shfl_xor_sync(0xffffffffu, e0, o));
                    e1 = max(e1, __shfl_xor_sync(0xffffffffu, e1, o));
                }
                if (lane < 4) {
                    int n0 = 8 * j + 2 * lane;
                    atomicMax(&g_maxbits[im0 * NB + n0],     e0);
                    atomicMax(&g_maxbits[im0 * NB + n0 + 1], e1);
                }
            }
        } else {
            // straddles an image boundary (rare): per-element atomics
            const int iml = gpl / NPATIMG;
            const int imh = (gpl + 8) / NPATIMG;
            #pragma unroll
            for (int j = 0; j < 32; j++) {
                int n0 = 8 * j + 2 * (lane & 3);
                atomicMax(&g_maxbits[iml * NB + n0],     enc_f(shneg(r[j][0])));
                atomicMax(&g_maxbits[iml * NB + n0 + 1], enc_f(shneg(r[j][1])));
                atomicMax(&g_maxbits[imh * NB + n0],     enc_f(shneg(r[j][2])));
                atomicMax(&g_maxbits[imh * NB + n0 + 1], enc_f(shneg(r[j][3])));
            }
        }
    }
}

// ---------------- K4: decode running max to output ----------------
__global__ void finalize_kernel(float* __restrict__ out) {
    int idx = blockIdx.x * NB + threadIdx.x;
    unsigned int k = g_maxbits[idx];
    out[idx] = (k & 0x80000000u) ? __uint_as_float(k & 0x7fffffffu)
                                 : __uint_as_float(~k);
}

// ---------------- launch ----------------
extern "C" void kernel_launch(void* const* d_in, const int* in_sizes, int n_in,
                              void* d_out, int out_size) {
    const float* image = (const float*)d_in[0];
    const float* dict  = (const float*)d_in[1];
    float* out = (float*)d_out;

    cudaFuncSetAttribute(b_mma_kernel,       cudaFuncAttributeMaxDynamicSharedMemorySize, B2_SMEM);
    cudaFuncSetAttribute(lca_persist_kernel, cudaFuncAttributeMaxDynamicSharedMemorySize, LCA_SMEM);

    init_kernel<<<NIMG, NB>>>();
    gram_kernel<<<NB, 256>>>(dict);
    dfrag_kernel<<<192, 256>>>(dict);
    b_mma_kernel<<<NIMG * 7, 512, B2_SMEM>>>(image);
    lca_persist_kernel<<<148, 256, LCA_SMEM>>>();
    finalize_kernel<<<NIMG, NB>>>(out);
}